// round 16
// baseline (speedup 1.0000x reference)
#include <cuda_runtime.h>
#include <cuda_fp16.h>
#include <math.h>
#include <stdint.h>

// Problem constants
#define BATCH 8
#define CIN   256
#define COUT  256
#define H     64
#define W     64
#define KTAP  9
#define Y_ELEMS (BATCH*COUT*H*W)          // 8388608

// Scratch (device globals — no cudaMalloc allowed)
__device__ float g_offmask[BATCH * 27 * H * W];       // 3.5 MB
__device__ __half g_xh[BATCH * CIN * H * W];          // 16 MB, x in fp16
// Deconv A fp16 frags: [cls(4)][mt(2)][ks(64)][m16t(8)][lane(32)][frag(4)] u32(half2)
#define WA_ELEMS (4 * 2 * 64 * 8 * 32 * 4)            // 524288
__device__ uint32_t g_wA[WA_ELEMS];
// Deform A fp16 frags, K=2304 unpadded: [mt(2)][ks(144)][m16t(8)][lane(32)][frag(4)]
#define WD_ELEMS (2 * 144 * 8 * 32 * 4)               // 294912
__device__ uint32_t g_wD2[WD_ELEMS];
// Offset-conv A fp16 frags, K=2304: [ks(144)][m16t(2)][lane(32)][frag(4)]
#define WO_ELEMS (144 * 2 * 32 * 4)                   // 36864
__device__ uint32_t g_wO[WO_ELEMS];

// ---------------------------------------------------------------------------
// Helpers
// ---------------------------------------------------------------------------
__device__ __forceinline__ uint32_t pack_h2(float lo, float hi) {
    uint32_t u;
    asm("cvt.rn.f16x2.f32 %0, %1, %2;" : "=r"(u) : "f"(hi), "f"(lo));
    return u;
}
__device__ __forceinline__ void mma_f16(float& d0, float& d1, float& d2, float& d3,
                                        uint32_t a0, uint32_t a1, uint32_t a2, uint32_t a3,
                                        uint32_t b0, uint32_t b1) {
    asm volatile("mma.sync.aligned.m16n8k16.row.col.f32.f16.f16.f32 "
                 "{%0,%1,%2,%3}, {%4,%5,%6,%7}, {%8,%9}, {%0,%1,%2,%3};"
                 : "+f"(d0), "+f"(d1), "+f"(d2), "+f"(d3)
                 : "r"(a0), "r"(a1), "r"(a2), "r"(a3), "r"(b0), "r"(b1));
}
__device__ __forceinline__ uint32_t smem_u32(const void* p) {
    uint32_t a;
    asm("{ .reg .u64 t; cvta.to.shared.u64 t, %1; cvt.u32.u64 %0, t; }" : "=r"(a) : "l"(p));
    return a;
}
#define CP_ASYNC16(dst_u32, src_ptr) \
    asm volatile("cp.async.cg.shared.global [%0], [%1], 16;" :: "r"(dst_u32), "l"(src_ptr))
#define CP_COMMIT() asm volatile("cp.async.commit_group;" ::: "memory")
#define CP_WAIT0()  asm volatile("cp.async.wait_group 0;" ::: "memory")

// ---------------------------------------------------------------------------
// Kernel 0a: convert x to fp16 copy.
// ---------------------------------------------------------------------------
__global__ void k_prep_xh(const float* __restrict__ x) {
    int i = blockIdx.x * 256 + threadIdx.x;   // 2,097,152 total (8192 blocks)
    float4 v = ((const float4*)x)[i];
    uint2 o;
    o.x = pack_h2(v.x, v.y);
    o.y = pack_h2(v.z, v.w);
    ((uint2*)g_xh)[i] = o;
}

// ---------------------------------------------------------------------------
// Kernel 0b: bake deconv A fp16 fragments.
// ---------------------------------------------------------------------------
__global__ void k_prep_wA(const float* __restrict__ w_up) {
    int e = blockIdx.x * 256 + threadIdx.x;   // 524288 total (2048 blocks)
    if (e >= WA_ELEMS) return;
    int frag = e & 3;
    int lane = (e >> 2) & 31;
    int m16t = (e >> 7) & 7;
    int ks   = (e >> 10) & 63;
    int mt   = (e >> 16) & 1;
    int cls  = e >> 17;
    int a = cls >> 1, qb = cls & 1;
    int g = lane >> 2, tg = lane & 3;
    int o = mt * 128 + m16t * 16 + g + 8 * (frag & 1);
    int k0 = ks * 16 + 2 * tg + 8 * (frag >> 1);
    float v[2];
#pragma unroll
    for (int i = 0; i < 2; i++) {
        int kk = k0 + i;
        int c = kk >> 2, s = (kk >> 1) & 1, t = kk & 1;
        v[i] = w_up[((c << 8) + o) * 16 + (3 - (a + 2 * s)) * 4 + (3 - (qb + 2 * t))];
    }
    g_wA[e] = pack_h2(v[0], v[1]);
}

// ---------------------------------------------------------------------------
// Kernel 0c: bake deform A fp16 fragments, K=2304 unpadded (kk = c*9 + tap).
// ---------------------------------------------------------------------------
__global__ void k_prep_wD(const float* __restrict__ w_dcn) {
    int e = blockIdx.x * 256 + threadIdx.x;   // 294912 total (1152 blocks)
    if (e >= WD_ELEMS) return;
    int frag = e & 3;
    int lane = (e >> 2) & 31;
    int m16t = (e >> 7) & 7;
    int ks   = (e >> 10) % 144;
    int mt   = (e >> 10) / 144;
    int g = lane >> 2, tg = lane & 3;
    int o = mt * 128 + m16t * 16 + g + 8 * (frag & 1);
    int k0 = ks * 16 + 2 * tg + 8 * (frag >> 1);
    float v[2];
#pragma unroll
    for (int i = 0; i < 2; i++) {
        int kk = k0 + i;
        int c = kk / 9;
        int tap = kk - c * 9;
        v[i] = w_dcn[(o * 256 + c) * 9 + tap];
    }
    g_wD2[e] = pack_h2(v[0], v[1]);
}

// ---------------------------------------------------------------------------
// Kernel 0d: bake offset-conv A fp16 fragments, K=2304 unpadded.
// ---------------------------------------------------------------------------
__global__ void k_prep_wO(const float* __restrict__ w_off) {
    int e = blockIdx.x * 256 + threadIdx.x;   // 36864 total (144 blocks)
    if (e >= WO_ELEMS) return;
    int frag = e & 3;
    int lane = (e >> 2) & 31;
    int m16t = (e >> 7) & 1;
    int ks   = e >> 8;                  // 0..143
    int g = lane >> 2, tg = lane & 3;
    int o = m16t * 16 + g + 8 * (frag & 1);
    int k0 = ks * 16 + 2 * tg + 8 * (frag >> 1);
    float v[2];
#pragma unroll
    for (int i = 0; i < 2; i++) {
        int kk = k0 + i;
        int c = kk / 9;
        int tap = kk - c * 9;
        v[i] = (o < 27) ? w_off[(o * 256 + c) * 9 + tap] : 0.f;
    }
    g_wO[e] = pack_h2(v[0], v[1]);
}

// ---------------------------------------------------------------------------
// Kernel 1: offset conv fp16 MMA GEMM, K=2304, 144 chunks of 1 kstep(16).
// Grid 256: [b(8)][ht(32)].  CTA: M=32, N=128 px (2 rows).  (R13 proven)
// ---------------------------------------------------------------------------
__global__ void __launch_bounds__(256) k_off_mma(const float* __restrict__ b_off) {
    __shared__ uint32_t Bs[2][128 * 10];   // half[128][20] per buffer

    int tid = threadIdx.x;
    int wid = tid >> 5, lane = tid & 31;
    int g = lane >> 2, tg = lane & 3;

    int bidx = blockIdx.x;
    int ht = bidx & 31;
    int b = bidx >> 5;
    int h0 = ht << 1;
    int pix0 = h0 << 6;

    int half_ = tid >> 7;
    int pix = tid & 127;
    int r = pix >> 6, wc = pix & 63;
    int kbase = half_ << 3;
    const __half* xb = g_xh + (b << 20);

    float acc[2][2][4];
#pragma unroll
    for (int i = 0; i < 2; i++)
#pragma unroll
        for (int j = 0; j < 2; j++)
#pragma unroll
            for (int f = 0; f < 4; f++) acc[i][j][f] = 0.f;

    auto loadk = [&](int chunk, float* pv) {
#pragma unroll
        for (int q = 0; q < 8; q++) {
            int kk = chunk * 16 + kbase + q;
            int c = kk / 9;
            int tap = kk - c * 9;
            int dy = tap / 3;
            int dx = tap - dy * 3;
            int hh = h0 + r - 1 + dy;
            int ww = wc - 1 + dx;
            float v = 0.f;
            if (hh >= 0 && hh < H && ww >= 0 && ww < W)
                v = __half2float(__ldg(xb + (c << 12) + (hh << 6) + ww));
            pv[q] = v;
        }
    };

    {
        float pv[8];
        loadk(0, pv);
#pragma unroll
        for (int q = 0; q < 4; q++)
            Bs[0][pix * 10 + (half_ << 2) + q] = pack_h2(pv[2 * q], pv[2 * q + 1]);
    }
    __syncthreads();

    for (int chunk = 0; chunk < 144; chunk++) {
        int cur = chunk & 1;
        float pv[8];
        if (chunk < 143) loadk(chunk + 1, pv);
        uint32_t af[2][4];
#pragma unroll
        for (int mtl = 0; mtl < 2; mtl++) {
            uint4 q = *(const uint4*)(g_wO + ((chunk * 2 + mtl) * 32 + lane) * 4);
            af[mtl][0] = q.x; af[mtl][1] = q.y; af[mtl][2] = q.z; af[mtl][3] = q.w;
        }
        uint32_t bf[2][2];
#pragma unroll
        for (int nt = 0; nt < 2; nt++) {
            int nrow = wid * 16 + nt * 8 + g;
            bf[nt][0] = Bs[cur][nrow * 10 + tg];
            bf[nt][1] = Bs[cur][nrow * 10 + tg + 4];
        }
#pragma unroll
        for (int mtl = 0; mtl < 2; mtl++)
#pragma unroll
            for (int nt = 0; nt < 2; nt++)
                mma_f16(acc[mtl][nt][0], acc[mtl][nt][1], acc[mtl][nt][2], acc[mtl][nt][3],
                        af[mtl][0], af[mtl][1], af[mtl][2], af[mtl][3],
                        bf[nt][0], bf[nt][1]);
        if (chunk < 143) {
            int nxt = cur ^ 1;
#pragma unroll
            for (int q = 0; q < 4; q++)
                Bs[nxt][pix * 10 + (half_ << 2) + q] = pack_h2(pv[2 * q], pv[2 * q + 1]);
        }
        __syncthreads();
    }

#pragma unroll
    for (int mtl = 0; mtl < 2; mtl++)
#pragma unroll
        for (int hh = 0; hh < 2; hh++) {
            int o = mtl * 16 + g + hh * 8;
            if (o < 27) {
                float bo = __ldg(b_off + o);
                float* ob = g_offmask + ((b * 27 + o) << 12) + pix0;
#pragma unroll
                for (int nt = 0; nt < 2; nt++)
#pragma unroll
                    for (int cc = 0; cc < 2; cc++) {
                        int n = wid * 16 + nt * 8 + 2 * tg + cc;
                        ob[n] = acc[mtl][nt][hh * 2 + cc] + bo;
                    }
            }
        }
}

// ---------------------------------------------------------------------------
// Kernel 2: deformable conv fp16 GEMM, K=2304 unpadded, 6-slot fp16 stage ring.
// Grid 512: [b(8)][mt(2)][pt(32)].  CTA: M=128, N=128 px (2 rows), 144 ksteps.
// ONLY change vs R13: gather (tap, slot) carried incrementally — no divisions
// in the inner loop.
// Dyn smem: ring 6x8KB @0, Bs 1280u32 @49152, idx @54272, wgt @63488. total 81920
// ---------------------------------------------------------------------------
#define DEFORM_SMEM 81920
__global__ void __launch_bounds__(256) k_deform_mma(const float* __restrict__ g1,
                                                    const float* __restrict__ be1,
                                                    const float* __restrict__ m1,
                                                    const float* __restrict__ v1,
                                                    float* __restrict__ yout) {
    extern __shared__ char dsm[];
    __half*   stageh = (__half*)dsm;                     // [6][4096]
    uint32_t* BsB    = (uint32_t*)(dsm + 49152);         // [1280]
    ushort4*  s_idx  = (ushort4*)(dsm + 54272);          // [1152]
    float4*   s_wgt  = (float4*)(dsm + 63488);           // [1152]

    int tid = threadIdx.x;
    int wid = tid >> 5, lane = tid & 31;
    int g = lane >> 2, tg = lane & 3;
    int warpM = wid >> 2, warpN = wid & 3;

    int bidx = blockIdx.x;
    int pt = bidx & 31;
    int mt = (bidx >> 5) & 1;
    int b  = bidx >> 6;
    int pix0 = pt << 7;
    int h0 = pix0 >> 6;                 // two rows: h0, h0+1

    // ---- Phase A: tap table ----
    for (int e = tid; e < 1152; e += 256) {
        int pix = e / 9, tap = e - pix * 9;
        int h = h0 + (pix >> 6), w = pix & 63;
        const float* om = g_offmask + (b * 27) * 4096 + (h << 6) + w;
        float dy = om[tap * 4096];
        float dx = om[(9 + tap) * 4096];
        float ms = om[(18 + tap) * 4096];
        float m = 1.f / (1.f + expf(-ms));
        float py = dy + (float)(tap / 3 - 1 + h);
        float px = dx + (float)(tap % 3 - 1 + w);
        float fy = floorf(py), fx = floorf(px);
        float wy = py - fy, wx = px - fx;
        int y0 = (int)fy, x0 = (int)fx;
        int y1 = y0 + 1, x1 = x0 + 1;
        float vy0 = (y0 >= 0 && y0 < H) ? 1.f : 0.f;
        float vy1 = (y1 >= 0 && y1 < H) ? 1.f : 0.f;
        float vx0 = (x0 >= 0 && x0 < W) ? 1.f : 0.f;
        float vx1 = (x1 >= 0 && x1 < W) ? 1.f : 0.f;
        int cy0 = min(max(y0, 0), H - 1), cy1 = min(max(y1, 0), H - 1);
        int cx0 = min(max(x0, 0), W - 1), cx1 = min(max(x1, 0), W - 1);
        ushort4 id;
        id.x = (unsigned short)((cy0 << 6) + cx0);
        id.y = (unsigned short)((cy0 << 6) + cx1);
        id.z = (unsigned short)((cy1 << 6) + cx0);
        id.w = (unsigned short)((cy1 << 6) + cx1);
        s_idx[e] = id;
        float4 wv;
        wv.x = (1.f - wy) * (1.f - wx) * m * vy0 * vx0;
        wv.y = (1.f - wy) * wx * m * vy0 * vx1;
        wv.z = wy * (1.f - wx) * m * vy1 * vx0;
        wv.w = wy * wx * m * vy1 * vx1;
        s_wgt[e] = wv;
    }

    const __half* xhb = g_xh + (b << 20);
    uint32_t stage_u = smem_u32(stageh);
    int khalf = tid >> 7;
    int pix = tid & 127;
    int pixbase = pix * 9;
    int bsbase = pix * 20 + khalf * 8;

    // prologue: stage channels of C(0)
    int next_c = 0;
    {
        int cm = 15 / 9;     // cmax(0) = 1
        for (; next_c <= cm; next_c++) {
            int slot = next_c % 6;
            const __half* src = xhb + (next_c << 12);
            uint32_t dst = stage_u + slot * 8192;
            CP_ASYNC16(dst + tid * 16, src + tid * 8);
            CP_ASYNC16(dst + 4096 + tid * 16, src + 2048 + tid * 8);
        }
        CP_COMMIT();
    }

    const uint32_t* Afrag = g_wD2 + mt * (144 * 8 * 32 * 4);

    float acc[4][4][4];
#pragma unroll
    for (int i = 0; i < 4; i++)
#pragma unroll
        for (int j = 0; j < 4; j++)
#pragma unroll
            for (int f = 0; f < 4; f++) acc[i][j][f] = 0.f;

    __half* Bh = (__half*)BsB;

    // incremental gather state for this thread's first value (k = ks*16 + khalf*8)
    int tt = khalf << 3;     // tap of first value
    int ss = 0;              // slot (= c % 6) of first value

    for (int ks = 0; ks < 144; ks++) {
        CP_WAIT0();
        __syncthreads();          // staged channels for C(ks) visible; Bs free
        if (ks < 143) {
            int cm = (16 * (ks + 1) + 15) / 9;
            for (; next_c <= cm; next_c++) {
                int slot = next_c % 6;
                const __half* src = xhb + (next_c << 12);
                uint32_t dst = stage_u + slot * 8192;
                CP_ASYNC16(dst + tid * 16, src + tid * 8);
                CP_ASYNC16(dst + 4096 + tid * 16, src + 2048 + tid * 8);
            }
        }
        CP_COMMIT();
        // gather kstep ks -> Bs (no divisions: tap/slot carried incrementally)
        {
            int t_ = tt, s_ = ss;
#pragma unroll
            for (int q = 0; q < 8; q++) {
                const __half* stg = stageh + (s_ << 12);
                int e = pixbase + t_;
                ushort4 id = s_idx[e];
                float4 wv = s_wgt[e];
                float v = wv.x * __half2float(stg[id.x]) + wv.y * __half2float(stg[id.y]) +
                          wv.z * __half2float(stg[id.z]) + wv.w * __half2float(stg[id.w]);
                Bh[bsbase + q] = __float2half_rn(v);
                t_++;
                if (t_ == 9) { t_ = 0; s_++; if (s_ == 6) s_ = 0; }
            }
        }
        // advance state by +16 k for next kstep
        if (tt < 2) { tt += 7; ss += 1; } else { tt -= 2; ss += 2; }
        if (ss >= 6) ss -= 6;
        __syncthreads();          // Bs ready
        // MMA: one kstep (k16)
        uint32_t af[4][4];
#pragma unroll
        for (int mtl = 0; mtl < 4; mtl++) {
            uint4 q = *(const uint4*)(Afrag + ((ks * 8 + warpM * 4 + mtl) * 32 + lane) * 4);
            af[mtl][0] = q.x; af[mtl][1] = q.y; af[mtl][2] = q.z; af[mtl][3] = q.w;
        }
        uint32_t bf[4][2];
#pragma unroll
        for (int nt = 0; nt < 4; nt++) {
            int nrow = warpN * 32 + nt * 8 + g;
            bf[nt][0] = BsB[nrow * 10 + tg];
            bf[nt][1] = BsB[nrow * 10 + tg + 4];
        }
#pragma unroll
        for (int mtl = 0; mtl < 4; mtl++)
#pragma unroll
            for (int nt = 0; nt < 4; nt++)
                mma_f16(acc[mtl][nt][0], acc[mtl][nt][1], acc[mtl][nt][2], acc[mtl][nt][3],
                        af[mtl][0], af[mtl][1], af[mtl][2], af[mtl][3],
                        bf[nt][0], bf[nt][1]);
    }

    // ---- epilogue: BN1 + ReLU ----
#pragma unroll
    for (int mtl = 0; mtl < 4; mtl++)
#pragma unroll
        for (int hh = 0; hh < 2; hh++) {
            int o = mt * 128 + warpM * 64 + mtl * 16 + g + hh * 8;
            float s_ = __ldg(g1 + o) * rsqrtf(__ldg(v1 + o) + 1e-5f);
            float sh = __ldg(be1 + o) - __ldg(m1 + o) * s_;
            float* ob = yout + (((b << 8) + o) << 12) + pix0;
#pragma unroll
            for (int nt = 0; nt < 4; nt++)
#pragma unroll
                for (int cc = 0; cc < 2; cc++) {
                    int n = warpN * 32 + nt * 8 + 2 * tg + cc;
                    float v = acc[mtl][nt][hh * 2 + cc];
                    ob[n] = fmaxf(fmaf(v, s_, sh), 0.f);
                }
        }
}

// ---------------------------------------------------------------------------
// Kernel 3: transposed conv fp16 GEMM + BN2 + ReLU.  K-chunk=32 (R13 proven).
// Grid 2048: [cls(4)][b(8)][mt(2)][pt(32)].  CTA: M=128, N=128, K=1024,
// 32 chunks of 2 ksteps.  Bs: half[128][36] per buffer (u32 stride 18).
// ---------------------------------------------------------------------------
__global__ void __launch_bounds__(256) k_deconv_mma(const float* __restrict__ y,
                                                    const float* __restrict__ g2,
                                                    const float* __restrict__ be2,
                                                    const float* __restrict__ m2,
                                                    const float* __restrict__ v2,
                                                    float* __restrict__ up) {
    __shared__ uint32_t Bs[2][128 * 18];   // half[128][36] per buffer

    int tid = threadIdx.x;
    int wid = tid >> 5, lane = tid & 31;
    int g = lane >> 2, tg = lane & 3;
    int warpM = wid >> 2, warpN = wid & 3;

    int bidx = blockIdx.x;
    int pt  = bidx & 31;
    int mt  = (bidx >> 5) & 1;
    int b   = (bidx >> 6) & 7;
    int cls = bidx >> 9;
    int a = cls >> 1, qb = cls & 1;
    int pp0 = pt << 1;

    int kl = tid & 15;
    int nb = tid >> 4;
    int c_l = kl >> 2, s = (kl >> 1) & 1, t = kl & 1;
    int pr = nb >> 3;
    int qq0 = (nb & 7) << 3;
    int n0 = nb << 3;
    int iy = pp0 + pr + s + a - 1;
    bool rowok = (iy >= 0 && iy < H);
    const float* ybase = y + ((b << 8) << 12) + (iy << 6);
    int ix0 = qq0 + qb - 1 + t;

    float acc[4][4][4];
#pragma unroll
    for (int i = 0; i < 4; i++)
#pragma unroll
        for (int j = 0; j < 4; j++)
#pragma unroll
            for (int f = 0; f < 4; f++) acc[i][j][f] = 0.f;

    auto fillchunk = [&](int chunk, float* pv) {
#pragma unroll
        for (int hf = 0; hf < 2; hf++) {
            const float* yr = ybase + ((chunk * 8 + hf * 4 + c_l) << 12);
#pragma unroll
            for (int j = 0; j < 8; j++) {
                int ix = ix0 + j;
                pv[hf * 8 + j] = (rowok && ix >= 0 && ix < W) ? __ldg(yr + ix) : 0.f;
            }
        }
    };
    auto storechunk = [&](int buf, const float* pv) {
        __half* Bh = (__half*)Bs[buf];
#pragma unroll
        for (int hf = 0; hf < 2; hf++)
#pragma unroll
            for (int j = 0; j < 8; j++)
                Bh[(n0 + j) * 36 + hf * 16 + kl] = __float2half_rn(pv[hf * 8 + j]);
    };

    {
        float pv[16];
        fillchunk(0, pv);
        storechunk(0, pv);
    }
    __syncthreads();

    const uint32_t* Afrag = g_wA + (cls * 2 + mt) * (64 * 8 * 32 * 4);

    for (int chunk = 0; chunk < 32; chunk++) {
        int cur = chunk & 1;
        float pv[16];
        if (chunk < 31) fillchunk(chunk + 1, pv);
#pragma unroll
        for (int ksv = 0; ksv < 2; ksv++) {
            int ks = chunk * 2 + ksv;
            uint32_t af[4][4];
#pragma unroll
            for (int mtl = 0; mtl < 4; mtl++) {
                uint4 q = *(const uint4*)(Afrag + ((ks * 8 + warpM * 4 + mtl) * 32 + lane) * 4);
                af[mtl][0] = q.x; af[mtl][1] = q.y; af[mtl][2] = q.z; af[mtl][3] = q.w;
            }
            uint32_t bf[4][2];
#pragma unroll
            for (int nt = 0; nt < 4; nt++) {
                int nrow = warpN * 32 + nt * 8 + g;
                bf[nt][0] = Bs[cur][nrow * 18 + ksv * 8 + tg];
                bf[nt][1] = Bs[cur][nrow * 18 + ksv * 8 + tg + 4];
            }
#pragma unroll
            for (int mtl = 0; mtl < 4; mtl++)
#pragma unroll
                for (int nt = 0; nt < 4; nt++)
                    mma_f16(acc[mtl][nt][0], acc[mtl][nt][1], acc[mtl][nt][2], acc[mtl][nt][3],
                            af[mtl][0], af[mtl][1], af[mtl][2], af[mtl][3],
                            bf[nt][0], bf[nt][1]);
        }
        if (chunk < 31) storechunk(cur ^ 1, pv);
        __syncthreads();
    }

    float sc[4][2], sh[4][2];
#pragma unroll
    for (int mtl = 0; mtl < 4; mtl++)
#pragma unroll
        for (int hh = 0; hh < 2; hh++) {
            int o = mt * 128 + warpM * 64 + mtl * 16 + g + hh * 8;
            float s_ = __ldg(g2 + o) * rsqrtf(__ldg(v2 + o) + 1e-5f);
            sc[mtl][hh] = s_;
            sh[mtl][hh] = __ldg(be2 + o) - __ldg(m2 + o) * s_;
        }
#pragma unroll
    for (int mtl = 0; mtl < 4; mtl++)
#pragma unroll
        for (int hh = 0; hh < 2; hh++) {
            int o = mt * 128 + warpM * 64 + mtl * 16 + g + hh * 8;
            float* ob = up + (((b << 8) + o) << 14);
#pragma unroll
            for (int nt = 0; nt < 4; nt++)
#pragma unroll
                for (int cc = 0; cc < 2; cc++) {
                    int n = warpN * 32 + nt * 8 + 2 * tg + cc;
                    int prr = n >> 6, qqv = n & 63;
                    int p = ((pp0 + prr) << 1) + a;
                    int qv = (qqv << 1) + qb;
                    float v = acc[mtl][nt][hh * 2 + cc];
                    ob[(p << 7) + qv] = fmaxf(fmaf(v, sc[mtl][hh], sh[mtl][hh]), 0.f);
                }
        }
}

// ---------------------------------------------------------------------------
extern "C" void kernel_launch(void* const* d_in, const int* in_sizes, int n_in,
                              void* d_out, int out_size) {
    const float* x      = (const float*)d_in[0];
    const float* w_off  = (const float*)d_in[1];
    const float* b_off  = (const float*)d_in[2];
    const float* w_dcn  = (const float*)d_in[3];
    const float* gamma1 = (const float*)d_in[4];
    const float* beta1  = (const float*)d_in[5];
    const float* mean1  = (const float*)d_in[6];
    const float* var1   = (const float*)d_in[7];
    const float* w_up   = (const float*)d_in[8];
    const float* gamma2 = (const float*)d_in[9];
    const float* beta2  = (const float*)d_in[10];
    const float* mean2  = (const float*)d_in[11];
    const float* var2   = (const float*)d_in[12];

    float* yout  = (float*)d_out;
    float* upout = yout + Y_ELEMS;

    cudaFuncSetAttribute(k_deform_mma, cudaFuncAttributeMaxDynamicSharedMemorySize, DEFORM_SMEM);

    k_prep_xh<<<8192, 256>>>(x);
    k_prep_wA<<<2048, 256>>>(w_up);
    k_prep_wD<<<1152, 256>>>(w_dcn);
    k_prep_wO<<<144, 256>>>(w_off);
    k_off_mma<<<256, 256>>>(b_off);
    k_deform_mma<<<512, 256, DEFORM_SMEM>>>(gamma1, beta1, mean1, var1, yout);
    k_deconv_mma<<<2048, 256>>>(yout, gamma2, beta2, mean2, var2, upout);
}

// round 17
// speedup vs baseline: 1.0526x; 1.0526x over previous
#include <cuda_runtime.h>
#include <cuda_fp16.h>
#include <math.h>
#include <stdint.h>

// Problem constants
#define BATCH 8
#define CIN   256
#define COUT  256
#define H     64
#define W     64
#define KTAP  9
#define Y_ELEMS (BATCH*COUT*H*W)          // 8388608

// Scratch (device globals — no cudaMalloc allowed)
__device__ float g_offmask[BATCH * 27 * H * W];       // 3.5 MB
__device__ __half g_xh[BATCH * CIN * H * W];          // 16 MB, x in fp16
// Deconv A fp16 frags: [cls(4)][mt(2)][ks(64)][m16t(8)][lane(32)][frag(4)] u32(half2)
#define WA_ELEMS (4 * 2 * 64 * 8 * 32 * 4)            // 524288
__device__ uint32_t g_wA[WA_ELEMS];
// Deform A fp16 frags, K=2304 unpadded: [mt(2)][ks(144)][m16t(8)][lane(32)][frag(4)]
#define WD_ELEMS (2 * 144 * 8 * 32 * 4)               // 294912
__device__ uint32_t g_wD2[WD_ELEMS];
// Offset-conv A fp16 frags, K=2304: [ks(144)][m16t(2)][lane(32)][frag(4)]
#define WO_ELEMS (144 * 2 * 32 * 4)                   // 36864
__device__ uint32_t g_wO[WO_ELEMS];

// ---------------------------------------------------------------------------
// Helpers
// ---------------------------------------------------------------------------
__device__ __forceinline__ uint32_t pack_h2(float lo, float hi) {
    uint32_t u;
    asm("cvt.rn.f16x2.f32 %0, %1, %2;" : "=r"(u) : "f"(hi), "f"(lo));
    return u;
}
__device__ __forceinline__ void mma_f16(float& d0, float& d1, float& d2, float& d3,
                                        uint32_t a0, uint32_t a1, uint32_t a2, uint32_t a3,
                                        uint32_t b0, uint32_t b1) {
    asm volatile("mma.sync.aligned.m16n8k16.row.col.f32.f16.f16.f32 "
                 "{%0,%1,%2,%3}, {%4,%5,%6,%7}, {%8,%9}, {%0,%1,%2,%3};"
                 : "+f"(d0), "+f"(d1), "+f"(d2), "+f"(d3)
                 : "r"(a0), "r"(a1), "r"(a2), "r"(a3), "r"(b0), "r"(b1));
}
__device__ __forceinline__ uint32_t smem_u32(const void* p) {
    uint32_t a;
    asm("{ .reg .u64 t; cvta.to.shared.u64 t, %1; cvt.u32.u64 %0, t; }" : "=r"(a) : "l"(p));
    return a;
}
#define CP_ASYNC16(dst_u32, src_ptr) \
    asm volatile("cp.async.cg.shared.global [%0], [%1], 16;" :: "r"(dst_u32), "l"(src_ptr))
#define CP_COMMIT() asm volatile("cp.async.commit_group;" ::: "memory")
#define CP_WAIT0()  asm volatile("cp.async.wait_group 0;" ::: "memory")

// ---------------------------------------------------------------------------
// Kernel 0a: convert x to fp16 copy.
// ---------------------------------------------------------------------------
__global__ void k_prep_xh(const float* __restrict__ x) {
    int i = blockIdx.x * 256 + threadIdx.x;   // 2,097,152 total (8192 blocks)
    float4 v = ((const float4*)x)[i];
    uint2 o;
    o.x = pack_h2(v.x, v.y);
    o.y = pack_h2(v.z, v.w);
    ((uint2*)g_xh)[i] = o;
}

// ---------------------------------------------------------------------------
// Kernel 0b: bake deconv A fp16 fragments.
// ---------------------------------------------------------------------------
__global__ void k_prep_wA(const float* __restrict__ w_up) {
    int e = blockIdx.x * 256 + threadIdx.x;   // 524288 total (2048 blocks)
    if (e >= WA_ELEMS) return;
    int frag = e & 3;
    int lane = (e >> 2) & 31;
    int m16t = (e >> 7) & 7;
    int ks   = (e >> 10) & 63;
    int mt   = (e >> 16) & 1;
    int cls  = e >> 17;
    int a = cls >> 1, qb = cls & 1;
    int g = lane >> 2, tg = lane & 3;
    int o = mt * 128 + m16t * 16 + g + 8 * (frag & 1);
    int k0 = ks * 16 + 2 * tg + 8 * (frag >> 1);
    float v[2];
#pragma unroll
    for (int i = 0; i < 2; i++) {
        int kk = k0 + i;
        int c = kk >> 2, s = (kk >> 1) & 1, t = kk & 1;
        v[i] = w_up[((c << 8) + o) * 16 + (3 - (a + 2 * s)) * 4 + (3 - (qb + 2 * t))];
    }
    g_wA[e] = pack_h2(v[0], v[1]);
}

// ---------------------------------------------------------------------------
// Kernel 0c: bake deform A fp16 fragments, K=2304 unpadded (kk = c*9 + tap).
// ---------------------------------------------------------------------------
__global__ void k_prep_wD(const float* __restrict__ w_dcn) {
    int e = blockIdx.x * 256 + threadIdx.x;   // 294912 total (1152 blocks)
    if (e >= WD_ELEMS) return;
    int frag = e & 3;
    int lane = (e >> 2) & 31;
    int m16t = (e >> 7) & 7;
    int ks   = (e >> 10) % 144;
    int mt   = (e >> 10) / 144;
    int g = lane >> 2, tg = lane & 3;
    int o = mt * 128 + m16t * 16 + g + 8 * (frag & 1);
    int k0 = ks * 16 + 2 * tg + 8 * (frag >> 1);
    float v[2];
#pragma unroll
    for (int i = 0; i < 2; i++) {
        int kk = k0 + i;
        int c = kk / 9;
        int tap = kk - c * 9;
        v[i] = w_dcn[(o * 256 + c) * 9 + tap];
    }
    g_wD2[e] = pack_h2(v[0], v[1]);
}

// ---------------------------------------------------------------------------
// Kernel 0d: bake offset-conv A fp16 fragments, K=2304 unpadded.
// ---------------------------------------------------------------------------
__global__ void k_prep_wO(const float* __restrict__ w_off) {
    int e = blockIdx.x * 256 + threadIdx.x;   // 36864 total (144 blocks)
    if (e >= WO_ELEMS) return;
    int frag = e & 3;
    int lane = (e >> 2) & 31;
    int m16t = (e >> 7) & 1;
    int ks   = e >> 8;                  // 0..143
    int g = lane >> 2, tg = lane & 3;
    int o = m16t * 16 + g + 8 * (frag & 1);
    int k0 = ks * 16 + 2 * tg + 8 * (frag >> 1);
    float v[2];
#pragma unroll
    for (int i = 0; i < 2; i++) {
        int kk = k0 + i;
        int c = kk / 9;
        int tap = kk - c * 9;
        v[i] = (o < 27) ? w_off[(o * 256 + c) * 9 + tap] : 0.f;
    }
    g_wO[e] = pack_h2(v[0], v[1]);
}

// ---------------------------------------------------------------------------
// Kernel 1: offset conv fp16 MMA GEMM, K=2304, 144 chunks of 1 kstep(16).
// Grid 256: [b(8)][ht(32)].  CTA: M=32, N=128 px (2 rows).  (R13 proven)
// ---------------------------------------------------------------------------
__global__ void __launch_bounds__(256) k_off_mma(const float* __restrict__ b_off) {
    __shared__ uint32_t Bs[2][128 * 10];   // half[128][20] per buffer

    int tid = threadIdx.x;
    int wid = tid >> 5, lane = tid & 31;
    int g = lane >> 2, tg = lane & 3;

    int bidx = blockIdx.x;
    int ht = bidx & 31;
    int b = bidx >> 5;
    int h0 = ht << 1;
    int pix0 = h0 << 6;

    int half_ = tid >> 7;
    int pix = tid & 127;
    int r = pix >> 6, wc = pix & 63;
    int kbase = half_ << 3;
    const __half* xb = g_xh + (b << 20);

    float acc[2][2][4];
#pragma unroll
    for (int i = 0; i < 2; i++)
#pragma unroll
        for (int j = 0; j < 2; j++)
#pragma unroll
            for (int f = 0; f < 4; f++) acc[i][j][f] = 0.f;

    auto loadk = [&](int chunk, float* pv) {
#pragma unroll
        for (int q = 0; q < 8; q++) {
            int kk = chunk * 16 + kbase + q;
            int c = kk / 9;
            int tap = kk - c * 9;
            int dy = tap / 3;
            int dx = tap - dy * 3;
            int hh = h0 + r - 1 + dy;
            int ww = wc - 1 + dx;
            float v = 0.f;
            if (hh >= 0 && hh < H && ww >= 0 && ww < W)
                v = __half2float(__ldg(xb + (c << 12) + (hh << 6) + ww));
            pv[q] = v;
        }
    };

    {
        float pv[8];
        loadk(0, pv);
#pragma unroll
        for (int q = 0; q < 4; q++)
            Bs[0][pix * 10 + (half_ << 2) + q] = pack_h2(pv[2 * q], pv[2 * q + 1]);
    }
    __syncthreads();

    for (int chunk = 0; chunk < 144; chunk++) {
        int cur = chunk & 1;
        float pv[8];
        if (chunk < 143) loadk(chunk + 1, pv);
        uint32_t af[2][4];
#pragma unroll
        for (int mtl = 0; mtl < 2; mtl++) {
            uint4 q = *(const uint4*)(g_wO + ((chunk * 2 + mtl) * 32 + lane) * 4);
            af[mtl][0] = q.x; af[mtl][1] = q.y; af[mtl][2] = q.z; af[mtl][3] = q.w;
        }
        uint32_t bf[2][2];
#pragma unroll
        for (int nt = 0; nt < 2; nt++) {
            int nrow = wid * 16 + nt * 8 + g;
            bf[nt][0] = Bs[cur][nrow * 10 + tg];
            bf[nt][1] = Bs[cur][nrow * 10 + tg + 4];
        }
#pragma unroll
        for (int mtl = 0; mtl < 2; mtl++)
#pragma unroll
            for (int nt = 0; nt < 2; nt++)
                mma_f16(acc[mtl][nt][0], acc[mtl][nt][1], acc[mtl][nt][2], acc[mtl][nt][3],
                        af[mtl][0], af[mtl][1], af[mtl][2], af[mtl][3],
                        bf[nt][0], bf[nt][1]);
        if (chunk < 143) {
            int nxt = cur ^ 1;
#pragma unroll
            for (int q = 0; q < 4; q++)
                Bs[nxt][pix * 10 + (half_ << 2) + q] = pack_h2(pv[2 * q], pv[2 * q + 1]);
        }
        __syncthreads();
    }

#pragma unroll
    for (int mtl = 0; mtl < 2; mtl++)
#pragma unroll
        for (int hh = 0; hh < 2; hh++) {
            int o = mtl * 16 + g + hh * 8;
            if (o < 27) {
                float bo = __ldg(b_off + o);
                float* ob = g_offmask + ((b * 27 + o) << 12) + pix0;
#pragma unroll
                for (int nt = 0; nt < 2; nt++)
#pragma unroll
                    for (int cc = 0; cc < 2; cc++) {
                        int n = wid * 16 + nt * 8 + 2 * tg + cc;
                        ob[n] = acc[mtl][nt][hh * 2 + cc] + bo;
                    }
            }
        }
}

// ---------------------------------------------------------------------------
// Kernel 2: deformable conv fp16 GEMM, K=2304 unpadded, 8-slot fp16 stage ring,
// K-chunk=32 (2 ksteps per barrier pair).  72 iterations.
// Grid 512: [b(8)][mt(2)][pt(32)].  CTA: M=128, N=128 px (2 rows).
// Ring-slot safety: issued-max - read-min = floor((32i+63)/9) - floor(32i/9)
// <= 7 < 8, so slot = c % 8 never collides.
// Dyn smem: ring 8x8KB @0, Bs 18*128 u32 @65536 (9216B), idx @74752 (9216B),
//           wgt @83968 (18432B).  total 102400
// ---------------------------------------------------------------------------
#define DEFORM_SMEM 102400
__global__ void __launch_bounds__(256) k_deform_mma(const float* __restrict__ g1,
                                                    const float* __restrict__ be1,
                                                    const float* __restrict__ m1,
                                                    const float* __restrict__ v1,
                                                    float* __restrict__ yout) {
    extern __shared__ char dsm[];
    __half*   stageh = (__half*)dsm;                     // [8][4096]
    uint32_t* BsB    = (uint32_t*)(dsm + 65536);         // [128*18]
    ushort4*  s_idx  = (ushort4*)(dsm + 74752);          // [1152]
    float4*   s_wgt  = (float4*)(dsm + 83968);           // [1152]

    int tid = threadIdx.x;
    int wid = tid >> 5, lane = tid & 31;
    int g = lane >> 2, tg = lane & 3;
    int warpM = wid >> 2, warpN = wid & 3;

    int bidx = blockIdx.x;
    int pt = bidx & 31;
    int mt = (bidx >> 5) & 1;
    int b  = bidx >> 6;
    int pix0 = pt << 7;
    int h0 = pix0 >> 6;                 // two rows: h0, h0+1

    // ---- Phase A: tap table ----
    for (int e = tid; e < 1152; e += 256) {
        int pix = e / 9, tap = e - pix * 9;
        int h = h0 + (pix >> 6), w = pix & 63;
        const float* om = g_offmask + (b * 27) * 4096 + (h << 6) + w;
        float dy = om[tap * 4096];
        float dx = om[(9 + tap) * 4096];
        float ms = om[(18 + tap) * 4096];
        float m = 1.f / (1.f + expf(-ms));
        float py = dy + (float)(tap / 3 - 1 + h);
        float px = dx + (float)(tap % 3 - 1 + w);
        float fy = floorf(py), fx = floorf(px);
        float wy = py - fy, wx = px - fx;
        int y0 = (int)fy, x0 = (int)fx;
        int y1 = y0 + 1, x1 = x0 + 1;
        float vy0 = (y0 >= 0 && y0 < H) ? 1.f : 0.f;
        float vy1 = (y1 >= 0 && y1 < H) ? 1.f : 0.f;
        float vx0 = (x0 >= 0 && x0 < W) ? 1.f : 0.f;
        float vx1 = (x1 >= 0 && x1 < W) ? 1.f : 0.f;
        int cy0 = min(max(y0, 0), H - 1), cy1 = min(max(y1, 0), H - 1);
        int cx0 = min(max(x0, 0), W - 1), cx1 = min(max(x1, 0), W - 1);
        ushort4 id;
        id.x = (unsigned short)((cy0 << 6) + cx0);
        id.y = (unsigned short)((cy0 << 6) + cx1);
        id.z = (unsigned short)((cy1 << 6) + cx0);
        id.w = (unsigned short)((cy1 << 6) + cx1);
        s_idx[e] = id;
        float4 wv;
        wv.x = (1.f - wy) * (1.f - wx) * m * vy0 * vx0;
        wv.y = (1.f - wy) * wx * m * vy0 * vx1;
        wv.z = wy * (1.f - wx) * m * vy1 * vx0;
        wv.w = wy * wx * m * vy1 * vx1;
        s_wgt[e] = wv;
    }

    const __half* xhb = g_xh + (b << 20);
    uint32_t stage_u = smem_u32(stageh);
    int khalf = tid >> 7;
    int pix = tid & 127;
    int pixbase = pix * 9;

    // prologue: stage channels of chunk 0 (c 0..cmax(0)=floor(31/9)=3)
    int next_c = 0;
    {
        for (; next_c <= 3; next_c++) {
            int slot = next_c & 7;
            const __half* src = xhb + (next_c << 12);
            uint32_t dst = stage_u + slot * 8192;
            CP_ASYNC16(dst + tid * 16, src + tid * 8);
            CP_ASYNC16(dst + 4096 + tid * 16, src + 2048 + tid * 8);
        }
        CP_COMMIT();
    }

    const uint32_t* Afrag = g_wD2 + mt * (144 * 8 * 32 * 4);

    float acc[4][4][4];
#pragma unroll
    for (int i = 0; i < 4; i++)
#pragma unroll
        for (int j = 0; j < 4; j++)
#pragma unroll
            for (int f = 0; f < 4; f++) acc[i][j][f] = 0.f;

    __half* Bh = (__half*)BsB;

    for (int it = 0; it < 72; it++) {
        CP_WAIT0();
        __syncthreads();          // staged channels for chunk it visible; Bs free
        // issue cp for new channels of chunk it+1
        if (it < 71) {
            int cm = (32 * (it + 1) + 31) / 9;
            for (; next_c <= cm; next_c++) {
                int slot = next_c & 7;
                const __half* src = xhb + (next_c << 12);
                uint32_t dst = stage_u + slot * 8192;
                CP_ASYNC16(dst + tid * 16, src + tid * 8);
                CP_ASYNC16(dst + 4096 + tid * 16, src + 2048 + tid * 8);
            }
        }
        CP_COMMIT();
        // gather chunk it (2 ksteps, 16 values/thread) -> Bs
#pragma unroll
        for (int ksv = 0; ksv < 2; ksv++) {
            int kb = it * 32 + ksv * 16 + khalf * 8;
#pragma unroll
            for (int q = 0; q < 8; q++) {
                int k = kb + q;
                int c = k / 9;
                int tap = k - c * 9;
                int slot = c & 7;
                const __half* stg = stageh + (slot << 12);
                int e = pixbase + tap;
                ushort4 id = s_idx[e];
                float4 wv = s_wgt[e];
                float v = wv.x * __half2float(stg[id.x]) + wv.y * __half2float(stg[id.y]) +
                          wv.z * __half2float(stg[id.z]) + wv.w * __half2float(stg[id.w]);
                Bh[pix * 36 + ksv * 16 + khalf * 8 + q] = __float2half_rn(v);
            }
        }
        __syncthreads();          // Bs ready
        // MMA: 2 ksteps
#pragma unroll
        for (int ksv = 0; ksv < 2; ksv++) {
            int ks = it * 2 + ksv;
            uint32_t af[4][4];
#pragma unroll
            for (int mtl = 0; mtl < 4; mtl++) {
                uint4 q = *(const uint4*)(Afrag + ((ks * 8 + warpM * 4 + mtl) * 32 + lane) * 4);
                af[mtl][0] = q.x; af[mtl][1] = q.y; af[mtl][2] = q.z; af[mtl][3] = q.w;
            }
            uint32_t bf[4][2];
#pragma unroll
            for (int nt = 0; nt < 4; nt++) {
                int nrow = warpN * 32 + nt * 8 + g;
                bf[nt][0] = BsB[nrow * 18 + ksv * 8 + tg];
                bf[nt][1] = BsB[nrow * 18 + ksv * 8 + tg + 4];
            }
#pragma unroll
            for (int mtl = 0; mtl < 4; mtl++)
#pragma unroll
                for (int nt = 0; nt < 4; nt++)
                    mma_f16(acc[mtl][nt][0], acc[mtl][nt][1], acc[mtl][nt][2], acc[mtl][nt][3],
                            af[mtl][0], af[mtl][1], af[mtl][2], af[mtl][3],
                            bf[nt][0], bf[nt][1]);
        }
    }

    // ---- epilogue: BN1 + ReLU ----
#pragma unroll
    for (int mtl = 0; mtl < 4; mtl++)
#pragma unroll
        for (int hh = 0; hh < 2; hh++) {
            int o = mt * 128 + warpM * 64 + mtl * 16 + g + hh * 8;
            float s_ = __ldg(g1 + o) * rsqrtf(__ldg(v1 + o) + 1e-5f);
            float sh = __ldg(be1 + o) - __ldg(m1 + o) * s_;
            float* ob = yout + (((b << 8) + o) << 12) + pix0;
#pragma unroll
            for (int nt = 0; nt < 4; nt++)
#pragma unroll
                for (int cc = 0; cc < 2; cc++) {
                    int n = warpN * 32 + nt * 8 + 2 * tg + cc;
                    float v = acc[mtl][nt][hh * 2 + cc];
                    ob[n] = fmaxf(fmaf(v, s_, sh), 0.f);
                }
        }
}

// ---------------------------------------------------------------------------
// Kernel 3: transposed conv fp16 GEMM + BN2 + ReLU.  K-chunk=32 (R13 proven).
// Grid 2048: [cls(4)][b(8)][mt(2)][pt(32)].  CTA: M=128, N=128, K=1024,
// 32 chunks of 2 ksteps.  Bs: half[128][36] per buffer (u32 stride 18).
// ---------------------------------------------------------------------------
__global__ void __launch_bounds__(256) k_deconv_mma(const float* __restrict__ y,
                                                    const float* __restrict__ g2,
                                                    const float* __restrict__ be2,
                                                    const float* __restrict__ m2,
                                                    const float* __restrict__ v2,
                                                    float* __restrict__ up) {
    __shared__ uint32_t Bs[2][128 * 18];   // half[128][36] per buffer

    int tid = threadIdx.x;
    int wid = tid >> 5, lane = tid & 31;
    int g = lane >> 2, tg = lane & 3;
    int warpM = wid >> 2, warpN = wid & 3;

    int bidx = blockIdx.x;
    int pt  = bidx & 31;
    int mt  = (bidx >> 5) & 1;
    int b   = (bidx >> 6) & 7;
    int cls = bidx >> 9;
    int a = cls >> 1, qb = cls & 1;
    int pp0 = pt << 1;

    int kl = tid & 15;
    int nb = tid >> 4;
    int c_l = kl >> 2, s = (kl >> 1) & 1, t = kl & 1;
    int pr = nb >> 3;
    int qq0 = (nb & 7) << 3;
    int n0 = nb << 3;
    int iy = pp0 + pr + s + a - 1;
    bool rowok = (iy >= 0 && iy < H);
    const float* ybase = y + ((b << 8) << 12) + (iy << 6);
    int ix0 = qq0 + qb - 1 + t;

    float acc[4][4][4];
#pragma unroll
    for (int i = 0; i < 4; i++)
#pragma unroll
        for (int j = 0; j < 4; j++)
#pragma unroll
            for (int f = 0; f < 4; f++) acc[i][j][f] = 0.f;

    auto fillchunk = [&](int chunk, float* pv) {
#pragma unroll
        for (int hf = 0; hf < 2; hf++) {
            const float* yr = ybase + ((chunk * 8 + hf * 4 + c_l) << 12);
#pragma unroll
            for (int j = 0; j < 8; j++) {
                int ix = ix0 + j;
                pv[hf * 8 + j] = (rowok && ix >= 0 && ix < W) ? __ldg(yr + ix) : 0.f;
            }
        }
    };
    auto storechunk = [&](int buf, const float* pv) {
        __half* Bh = (__half*)Bs[buf];
#pragma unroll
        for (int hf = 0; hf < 2; hf++)
#pragma unroll
            for (int j = 0; j < 8; j++)
                Bh[(n0 + j) * 36 + hf * 16 + kl] = __float2half_rn(pv[hf * 8 + j]);
    };

    {
        float pv[16];
        fillchunk(0, pv);
        storechunk(0, pv);
    }
    __syncthreads();

    const uint32_t* Afrag = g_wA + (cls * 2 + mt) * (64 * 8 * 32 * 4);

    for (int chunk = 0; chunk < 32; chunk++) {
        int cur = chunk & 1;
        float pv[16];
        if (chunk < 31) fillchunk(chunk + 1, pv);
#pragma unroll
        for (int ksv = 0; ksv < 2; ksv++) {
            int ks = chunk * 2 + ksv;
            uint32_t af[4][4];
#pragma unroll
            for (int mtl = 0; mtl < 4; mtl++) {
                uint4 q = *(const uint4*)(Afrag + ((ks * 8 + warpM * 4 + mtl) * 32 + lane) * 4);
                af[mtl][0] = q.x; af[mtl][1] = q.y; af[mtl][2] = q.z; af[mtl][3] = q.w;
            }
            uint32_t bf[4][2];
#pragma unroll
            for (int nt = 0; nt < 4; nt++) {
                int nrow = warpN * 32 + nt * 8 + g;
                bf[nt][0] = Bs[cur][nrow * 18 + ksv * 8 + tg];
                bf[nt][1] = Bs[cur][nrow * 18 + ksv * 8 + tg + 4];
            }
#pragma unroll
            for (int mtl = 0; mtl < 4; mtl++)
#pragma unroll
                for (int nt = 0; nt < 4; nt++)
                    mma_f16(acc[mtl][nt][0], acc[mtl][nt][1], acc[mtl][nt][2], acc[mtl][nt][3],
                            af[mtl][0], af[mtl][1], af[mtl][2], af[mtl][3],
                            bf[nt][0], bf[nt][1]);
        }
        if (chunk < 31) storechunk(cur ^ 1, pv);
        __syncthreads();
    }

    float sc[4][2], sh[4][2];
#pragma unroll
    for (int mtl = 0; mtl < 4; mtl++)
#pragma unroll
        for (int hh = 0; hh < 2; hh++) {
            int o = mt * 128 + warpM * 64 + mtl * 16 + g + hh * 8;
            float s_ = __ldg(g2 + o) * rsqrtf(__ldg(v2 + o) + 1e-5f);
            sc[mtl][hh] = s_;
            sh[mtl][hh] = __ldg(be2 + o) - __ldg(m2 + o) * s_;
        }
#pragma unroll
    for (int mtl = 0; mtl < 4; mtl++)
#pragma unroll
        for (int hh = 0; hh < 2; hh++) {
            int o = mt * 128 + warpM * 64 + mtl * 16 + g + hh * 8;
            float* ob = up + (((b << 8) + o) << 14);
#pragma unroll
            for (int nt = 0; nt < 4; nt++)
#pragma unroll
                for (int cc = 0; cc < 2; cc++) {
                    int n = warpN * 32 + nt * 8 + 2 * tg + cc;
                    int prr = n >> 6, qqv = n & 63;
                    int p = ((pp0 + prr) << 1) + a;
                    int qv = (qqv << 1) + qb;
                    float v = acc[mtl][nt][hh * 2 + cc];
                    ob[(p << 7) + qv] = fmaxf(fmaf(v, sc[mtl][hh], sh[mtl][hh]), 0.f);
                }
        }
}

// ---------------------------------------------------------------------------
extern "C" void kernel_launch(void* const* d_in, const int* in_sizes, int n_in,
                              void* d_out, int out_size) {
    const float* x      = (const float*)d_in[0];
    const float* w_off  = (const float*)d_in[1];
    const float* b_off  = (const float*)d_in[2];
    const float* w_dcn  = (const float*)d_in[3];
    const float* gamma1 = (const float*)d_in[4];
    const float* beta1  = (const float*)d_in[5];
    const float* mean1  = (const float*)d_in[6];
    const float* var1   = (const float*)d_in[7];
    const float* w_up   = (const float*)d_in[8];
    const float* gamma2 = (const float*)d_in[9];
    const float* beta2  = (const float*)d_in[10];
    const float* mean2  = (const float*)d_in[11];
    const float* var2   = (const float*)d_in[12];

    float* yout  = (float*)d_out;
    float* upout = yout + Y_ELEMS;

    cudaFuncSetAttribute(k_deform_mma, cudaFuncAttributeMaxDynamicSharedMemorySize, DEFORM_SMEM);

    k_prep_xh<<<8192, 256>>>(x);
    k_prep_wA<<<2048, 256>>>(w_up);
    k_prep_wD<<<1152, 256>>>(w_dcn);
    k_prep_wO<<<144, 256>>>(w_off);
    k_off_mma<<<256, 256>>>(b_off);
    k_deform_mma<<<512, 256, DEFORM_SMEM>>>(gamma1, beta1, mean1, var1, yout);
    k_deconv_mma<<<2048, 256>>>(yout, gamma2, beta2, mean2, var2, upout);
}